// round 7
// baseline (speedup 1.0000x reference)
#include <cuda_runtime.h>
#include <cstdint>

#define N_GAUSS   16
#define N_ATOMS   3072
#define N_GRAPHS  64
#define K_GRID    4096

// Table: per atom, 512 cubic intervals over t = 8*r2. Interval i = round(t)
// covers t in [i-0.5, i+0.5]; local parameter u = t - i in [-0.5, 0.5].
#define NNODES    512
#define TSCALE    8.0f
#define TCLAMP    511.49f
#define ABYTES    (NNODES * 16)     // 8 KB per atom table

#define BLOCK     512
#define PPT       2
#define CHUNK     (BLOCK*PPT)       // 1024
#define NCHUNK    (K_GRID/CHUNK)    // 4
#define ASPLIT    2                 // atom-range split -> 512 blocks total

#define GROUP     2                 // atoms per pipeline step
#define NBUF      2
#define ACAP      512               // atom-coord smem per tile (n/2 << 512)

__device__ float4 g_table[N_ATOMS * NNODES];   // ~25 MB scratch

__device__ __forceinline__ float ex2f(float x) {
    float y; asm("ex2.approx.ftz.f32 %0, %1;" : "=f"(y) : "f"(x)); return y;
}
__device__ __forceinline__ uint32_t s2u(const void* p) {
    return (uint32_t)__cvta_generic_to_shared(p);
}
__device__ __forceinline__ void mbar_init(uint32_t a, uint32_t cnt) {
    asm volatile("mbarrier.init.shared.b64 [%0], %1;" :: "r"(a), "r"(cnt) : "memory");
}
__device__ __forceinline__ void mbar_expect_tx(uint32_t a, uint32_t tx) {
    asm volatile("mbarrier.arrive.expect_tx.shared.b64 _, [%0], %1;" :: "r"(a), "r"(tx) : "memory");
}
__device__ __forceinline__ void bulk_g2s(uint32_t dst, const void* src,
                                         uint32_t sz, uint32_t mbar) {
    asm volatile("cp.async.bulk.shared::cluster.global.mbarrier::complete_tx::bytes"
                 " [%0], [%1], %2, [%3];"
                 :: "r"(dst), "l"(src), "r"(sz), "r"(mbar) : "memory");
}
__device__ __forceinline__ void mbar_wait(uint32_t mbar, uint32_t phase) {
    asm volatile(
        "{\n\t"
        ".reg .pred P;\n\t"
        "WAIT_%=:\n\t"
        "mbarrier.try_wait.parity.acquire.cta.shared::cta.b64 P, [%0], %1;\n\t"
        "@P bra.uni DONE_%=;\n\t"
        "bra.uni WAIT_%=;\n\t"
        "DONE_%=:\n\t"
        "}" :: "r"(mbar), "r"(phase) : "memory");
}

// ---------------------------------------------------------------------------
// Build: per-atom center-shifted Hermite-cubic table. Node k at t = k-0.5.
// Uniform node spacing in r2 => exp recurrence: e(k+1) = e(k) * step_j.
// Each thread computes 4 contiguous nodes: 1 MUFU + 3 FMUL per gaussian.
__global__ __launch_bounds__(128)
void build_kernel(const float* __restrict__ coeff) {
    const int atom = blockIdx.x;
    const int tid  = threadIdx.x;
    __shared__ float w[N_GAUSS], wc[N_GAUSS], fstep[N_GAUSS];
    __shared__ float fv[NNODES + 1], mv[NNODES + 1];

    if (tid < N_GAUSS) {
        int j = tid;
        float sigma = 0.5f + 0.3f * (float)j;
        float tt = sigma * 2.5066282746310002f;      // sigma*sqrt(2*pi)
        float sr = 1.0f / (tt * tt * tt);
        float cj = 1.0f / (sigma * sigma);
        float wj = coeff[atom * N_GAUSS + j] * sr;
        w[j]  = wj;
        wc[j] = wj * cj * (1.0f / TSCALE);           // df/dt = -sum wc*e
        float cL = 1.4426950408889634f * cj;         // log2e/sigma^2
        fstep[j] = ex2f(-cL * (1.0f / TSCALE));      // per-node decay factor
    }
    __syncthreads();

    {
        const int k0 = 4 * tid;                      // nodes k0..k0+3
        float s1[4] = {0.f, 0.f, 0.f, 0.f};
        float s2[4] = {0.f, 0.f, 0.f, 0.f};
        const float r20 = ((float)k0 - 0.5f) * (1.0f / TSCALE);
        #pragma unroll
        for (int j = 0; j < N_GAUSS; j++) {
            float sigma = 0.5f + 0.3f * (float)j;
            float cL = 1.4426950408889634f / (sigma * sigma);
            float e  = ex2f(-r20 * cL);
            const float f = fstep[j];
            const float wj = w[j], wcj = wc[j];
            #pragma unroll
            for (int m = 0; m < 4; m++) {
                s1[m] = fmaf(wj,  e, s1[m]);
                s2[m] = fmaf(wcj, e, s2[m]);
                e *= f;
            }
        }
        #pragma unroll
        for (int m = 0; m < 4; m++) { fv[k0 + m] = s1[m]; mv[k0 + m] = -s2[m]; }
    }
    if (tid == 0) {                                  // node 512 (tail)
        float r2 = 511.5f * (1.0f / TSCALE);
        float s1 = 0.f, s2 = 0.f;
        #pragma unroll
        for (int j = 0; j < N_GAUSS; j++) {
            float sigma = 0.5f + 0.3f * (float)j;
            float cL = 1.4426950408889634f / (sigma * sigma);
            float e = ex2f(-r2 * cL);
            s1 = fmaf(w[j],  e, s1);
            s2 = fmaf(wc[j], e, s2);
        }
        fv[NNODES] = s1; mv[NNODES] = -s2;
    }
    __syncthreads();

    for (int i = tid; i < NNODES; i += 128) {
        float fL = fv[i], fR = fv[i + 1];
        float mL = mv[i], mR = mv[i + 1];
        float dd = fR - fL;
        float a0 = fL, a1 = mL;
        float a2 = 3.0f * dd - 2.0f * mL - mR;
        float a3 = mL + mR - 2.0f * dd;
        // Shift Hermite basis from v in [0,1] to u = v-0.5 in [-0.5,0.5]:
        float4 c;
        c.x = a0 + 0.5f * a1 + 0.25f * a2 + 0.125f * a3;
        c.y = a1 + a2 + 0.75f * a3;
        c.z = a2 + 1.5f * a3;
        c.w = a3;
        g_table[(size_t)atom * NNODES + i] = c;
    }
}

// ---------------------------------------------------------------------------
// Density: 512 blocks (4 chunks x 64 graphs x 2 atom-splits), 512 threads,
// 2 points/thread. Tables staged GROUP atoms/step via cp.async.bulk+mbarrier.
// Output accumulated with atomicAdd (d_out pre-zeroed by memset).
__global__ __launch_bounds__(BLOCK)
void density_kernel(const float* __restrict__ atom_coord,
                    const float* __restrict__ grid,
                    const int* __restrict__ braw,
                    float* __restrict__ out) {
    __shared__ __align__(16) float4 tbl[NBUF][GROUP][NNODES];   // 32 KB
    __shared__ float  sax[ACAP], say[ACAP], saz[ACAP];          // 6 KB
    __shared__ __align__(8) unsigned long long mbar[NBUF];
    __shared__ int s_flag, s_start, s_end;

    const int g   = blockIdx.y;
    const int tid = threadIdx.x;
    const uint32_t mb0 = s2u(&mbar[0]);
    const uint32_t mb1 = s2u(&mbar[1]);

    if (tid == 0) {
        s_flag = 0; s_start = N_ATOMS; s_end = N_ATOMS;
        mbar_init(mb0, 1);
        mbar_init(mb1, 1);
        asm volatile("fence.proxy.async.shared::cta;" ::: "memory");
    }
    __syncthreads();

    // dtype detect: int64 batch (values < 64) has all-zero odd words.
    int loc = 0;
    for (int i = 1 + 2 * tid; i < N_ATOMS; i += 2 * BLOCK) loc |= braw[i];
    if (loc) atomicOr(&s_flag, 1);
    __syncthreads();
    const bool is32 = (s_flag != 0);

    // Transition scan: start = first i with b[i]>=g, end = first with b[i]>=g+1.
    for (int i = tid; i < N_ATOMS; i += BLOCK) {
        int bi = is32 ? braw[i] : braw[2 * i];
        int bp = (i == 0) ? -1 : (is32 ? braw[i - 1] : braw[2 * i - 2]);
        if (bi >= g     && bp < g)     s_start = i;
        if (bi >= g + 1 && bp < g + 1) s_end   = i;
    }
    __syncthreads();

    // Atom-split: this block handles its half of the graph's atom range.
    const int n_all = s_end - s_start;
    const int half  = (n_all + 1) >> 1;
    const int aoff  = blockIdx.z * half;
    const int start = s_start + aoff;
    const int n     = min(n_all - aoff, half);       // may be <= 0 (handled)

    const float S = 2.8284271247461903f;  // sqrt(8): t = |S*(p-a)|^2 = 8*r2
    const float* gp = grid + (size_t)g * K_GRID * 3;
    const int kb = blockIdx.x * CHUNK + tid;

    float px[PPT], py[PPT], pz[PPT], acc[PPT];
    #pragma unroll
    for (int q = 0; q < PPT; q++) {
        const int k = kb + q * BLOCK;
        px[q] = gp[k * 3 + 0] * S;
        py[q] = gp[k * 3 + 1] * S;
        pz[q] = gp[k * 3 + 2] * S;
        acc[q] = 0.f;
    }

    uint32_t ph0 = 0, ph1 = 0;   // mbarrier phase parities (uniform)

    for (int base = 0; base < n; base += ACAP) {
        const int cnt = min(ACAP, n - base);
        const int A0  = start + base;
        const float4* src = g_table + (size_t)A0 * NNODES;

        __syncthreads();  // previous tile fully consumed
        for (int a = tid; a < cnt; a += BLOCK) {
            const float* ac = atom_coord + (size_t)(A0 + a) * 3;
            sax[a] = ac[0] * S;
            say[a] = ac[1] * S;
            saz[a] = ac[2] * S;
        }
        __syncthreads();  // coords visible (and tbl safe to overwrite)

        const int steps = (cnt + GROUP - 1) / GROUP;

        if (tid == 0) {
            {
                uint32_t sz = (uint32_t)min(GROUP, cnt) * ABYTES;
                mbar_expect_tx(mb0, sz);
                bulk_g2s(s2u(&tbl[0][0][0]), src, sz, mb0);
            }
            if (steps > 1) {
                uint32_t sz = (uint32_t)min(GROUP, cnt - GROUP) * ABYTES;
                mbar_expect_tx(mb1, sz);
                bulk_g2s(s2u(&tbl[1][0][0]), src + (size_t)GROUP * NNODES, sz, mb1);
            }
        }

        for (int s = 0; s < steps; s++) {
            const int buf = s & 1;
            if (buf == 0) { mbar_wait(mb0, ph0); ph0 ^= 1; }
            else          { mbar_wait(mb1, ph1); ph1 ^= 1; }

            const int a0 = s * GROUP;
            {
                const float ax = sax[a0], ay = say[a0], az = saz[a0];
                #pragma unroll
                for (int q = 0; q < PPT; q++) {
                    float dx = px[q] - ax, dy = py[q] - ay, dz = pz[q] - az;
                    float t = fmaf(dx, dx, fmaf(dy, dy, dz * dz));
                    t = fminf(t, TCLAMP);
                    float m = t + 8388608.0f;            // round(t) via 2^23
                    int   i = __float_as_int(m) & 0x3FF;
                    float u = t - (m - 8388608.0f);      // in [-0.5, 0.5]
                    float4 c = tbl[buf][0][i];
                    acc[q] += fmaf(fmaf(fmaf(c.w, u, c.z), u, c.y), u, c.x);
                }
            }
            if (a0 + 1 < cnt) {
                const float ax = sax[a0 + 1], ay = say[a0 + 1], az = saz[a0 + 1];
                #pragma unroll
                for (int q = 0; q < PPT; q++) {
                    float dx = px[q] - ax, dy = py[q] - ay, dz = pz[q] - az;
                    float t = fmaf(dx, dx, fmaf(dy, dy, dz * dz));
                    t = fminf(t, TCLAMP);
                    float m = t + 8388608.0f;
                    int   i = __float_as_int(m) & 0x3FF;
                    float u = t - (m - 8388608.0f);
                    float4 c = tbl[buf][1][i];
                    acc[q] += fmaf(fmaf(fmaf(c.w, u, c.z), u, c.y), u, c.x);
                }
            }

            __syncthreads();  // all reads of tbl[buf] complete
            if (tid == 0 && s + 2 < steps) {
                const int an = (s + 2) * GROUP;
                uint32_t sz = (uint32_t)min(GROUP, cnt - an) * ABYTES;
                uint32_t mb = buf ? mb1 : mb0;
                mbar_expect_tx(mb, sz);
                bulk_g2s(s2u(&tbl[buf][0][0]), src + (size_t)an * NNODES, sz, mb);
            }
        }
    }

    float* op = out + (size_t)g * K_GRID;
    #pragma unroll
    for (int q = 0; q < PPT; q++)
        atomicAdd(&op[kb + q * BLOCK], acc[q]);
}

// ---------------------------------------------------------------------------
extern "C" void kernel_launch(void* const* d_in, const int* in_sizes, int n_in,
                              void* d_out, int out_size) {
    const float* coeff      = (const float*)d_in[0];
    const float* atom_coord = (const float*)d_in[1];
    const float* grid       = (const float*)d_in[2];
    const int*   batch_raw  = (const int*)d_in[3];
    float* out = (float*)d_out;

    cudaMemsetAsync(out, 0, (size_t)out_size * sizeof(float));
    build_kernel<<<N_ATOMS, 128>>>(coeff);
    density_kernel<<<dim3(NCHUNK, N_GRAPHS, ASPLIT), BLOCK>>>(atom_coord, grid,
                                                              batch_raw, out);
}